// round 9
// baseline (speedup 1.0000x reference)
#include <cuda_runtime.h>
#include <cuda_bf16.h>
#include <math.h>
#include <stdint.h>

// ---------------- problem constants ----------------
#define MAXN 100000
#define MAXE 1000000
#define GG 250
#define NEGSLOPE 0.2f
#define SCAN_BLK 1024
#define SCAN_NB ((MAXN + SCAN_BLK - 1) / SCAN_BLK)

// ---------------- static device scratch ----------------
__device__ float g_bufA[MAXN * 128];   // L0 out (L1 input)
__device__ float g_gl[MAXN * 128];
__device__ float g_gr[MAXN * 128];
__device__ int   g_degi[MAXN], g_dego[MAXN];
__device__ int   g_rowI[MAXN], g_rowO[MAXN];
__device__ int   g_curI[MAXN], g_curO[MAXN];
__device__ int   g_partI[SCAN_NB + 32], g_partO[SCAN_NB + 32];
__device__ float g_dinvd[MAXN], g_dinvs[MAXN];
__device__ int   g_snode[MAXE];
__device__ float g_coefI[MAXE];
__device__ float g_eaI[MAXE];
__device__ int   g_dnode[MAXE];
__device__ float g_coefO[MAXE];
__device__ float g_cnt[GG];
__device__ float g_pool1[GG * 128], g_pool2[GG * 128];
__device__ float g_z[GG * 256];

// ---------------- helpers ----------------
__device__ __forceinline__ void red4(float* p, float a, float b, float c, float d) {
    asm volatile("red.global.add.v4.f32 [%0], {%1,%2,%3,%4};"
                 :: "l"(p), "f"(a), "f"(b), "f"(c), "f"(d) : "memory");
}
__device__ __forceinline__ float lrelu(float x) {
    return (x > 0.f) ? x : NEGSLOPE * x;
}
__device__ __forceinline__ uint32_t f2tf(float f) {
    uint32_t u;
    asm("cvt.rna.tf32.f32 %0, %1;" : "=r"(u) : "f"(f));
    return u;
}
__device__ __forceinline__ void mma_tf32(float c[4], const uint32_t a[4], uint32_t b0, uint32_t b1) {
    asm volatile(
        "mma.sync.aligned.m16n8k8.row.col.f32.tf32.tf32.f32 "
        "{%0,%1,%2,%3}, {%4,%5,%6,%7}, {%8,%9}, {%0,%1,%2,%3};"
        : "+f"(c[0]), "+f"(c[1]), "+f"(c[2]), "+f"(c[3])
        : "r"(a[0]), "r"(a[1]), "r"(a[2]), "r"(a[3]), "r"(b0), "r"(b1));
}

// ---------------- setup kernels ----------------
__global__ void zero_misc(int* degi, int* dego, float* cnt,
                          float* pool1, float* pool2, int nN) {
    int i = blockIdx.x * blockDim.x + threadIdx.x;
    if (i < nN) { degi[i] = 0; dego[i] = 0; }
    if (i < GG) cnt[i] = 0.f;
    if (i < GG * 128) { pool1[i] = 0.f; pool2[i] = 0.f; }
}

__global__ void deg_kernel(const int* __restrict__ src, const int* __restrict__ dst,
                           int* degi, int* dego, int nE) {
    int e = blockIdx.x * blockDim.x + threadIdx.x;
    if (e >= nE) return;
    atomicAdd(&degi[dst[e]], 1);
    atomicAdd(&dego[src[e]], 1);
}

__global__ void dinv_kernel(const int* __restrict__ degi, const int* __restrict__ dego,
                            float* dd, float* ds,
                            const int* __restrict__ batch, float* cnt, int n) {
    int i = blockIdx.x * blockDim.x + threadIdx.x;
    if (i >= n) return;
    int a = degi[i], b = dego[i];
    dd[i] = (a > 0) ? rsqrtf((float)a) : 0.f;
    ds[i] = (b > 0) ? rsqrtf((float)b) : 0.f;
    atomicAdd(&cnt[batch[i]], 1.f);
}

// exclusive scan, phase A
__global__ __launch_bounds__(SCAN_BLK) void scanA(
    const int* __restrict__ degi, const int* __restrict__ dego,
    int* rowI, int* rowO, int* partI, int* partO, int n)
{
    const int* in = blockIdx.y ? dego : degi;
    int* out = blockIdx.y ? rowO : rowI;
    int* part = blockIdx.y ? partO : partI;
    int i = blockIdx.x * SCAN_BLK + threadIdx.x;
    int v = (i < n) ? in[i] : 0;
    int lane = threadIdx.x & 31, wid = threadIdx.x >> 5;
    int p = v;
#pragma unroll
    for (int o = 1; o < 32; o <<= 1) { int t = __shfl_up_sync(~0u, p, o); if (lane >= o) p += t; }
    __shared__ int ws[32];
    if (lane == 31) ws[wid] = p;
    __syncthreads();
    if (wid == 0) {
        int s = ws[lane];
#pragma unroll
        for (int o = 1; o < 32; o <<= 1) { int t = __shfl_up_sync(~0u, s, o); if (lane >= o) s += t; }
        ws[lane] = s;
    }
    __syncthreads();
    int base = wid ? ws[wid - 1] : 0;
    if (i < n) out[i] = base + p - v;
    if (threadIdx.x == SCAN_BLK - 1) part[blockIdx.x] = base + p;
}

__global__ __launch_bounds__(128) void scanB(int* partI, int* partO, int nb) {
    int* part = blockIdx.x ? partO : partI;
    int tid = threadIdx.x;
    int v = (tid < nb) ? part[tid] : 0;
    int lane = tid & 31, wid = tid >> 5;
    int p = v;
#pragma unroll
    for (int o = 1; o < 32; o <<= 1) { int t = __shfl_up_sync(~0u, p, o); if (lane >= o) p += t; }
    __shared__ int ws[4];
    if (lane == 31) ws[wid] = p;
    __syncthreads();
    int base = 0;
    for (int w = 0; w < wid; w++) base += ws[w];
    if (tid < nb) part[tid] = base + p - v;
}

__global__ __launch_bounds__(SCAN_BLK) void scanC(
    int* rowI, int* rowO, const int* __restrict__ partI, const int* __restrict__ partO,
    int* curI, int* curO, int n)
{
    int i = blockIdx.x * SCAN_BLK + threadIdx.x;
    if (i >= n) return;
    if (blockIdx.y == 0) { int r = rowI[i] + partI[blockIdx.x]; rowI[i] = r; curI[i] = r; }
    else                 { int r = rowO[i] + partO[blockIdx.x]; rowO[i] = r; curO[i] = r; }
}

__global__ __launch_bounds__(256) void build_perm(
    const int* __restrict__ src, const int* __restrict__ dst, const float* __restrict__ ea,
    const float* __restrict__ dinvd, const float* __restrict__ dinvs,
    int* curI, int* curO,
    int* snode, float* coefI, float* eaI,
    int* dnode, float* coefO, int nE)
{
    int e = blockIdx.x * blockDim.x + threadIdx.x;
    if (e >= nE) return;
    int s = src[e], d = dst[e];
    int pI = atomicAdd(&curI[d], 1);
    snode[pI] = s; coefI[pI] = dinvd[s]; eaI[pI] = ea[e];
    int pO = atomicAdd(&curO[s], 1);
    dnode[pO] = d; coefO[pO] = dinvs[d];
}

// ---------------- plain TF32 GEMM (for gl/gr transforms) ----------------
__global__ __launch_bounds__(256) void gemm_tf32(
    const float* __restrict__ A0, const float* __restrict__ W0,
    float* __restrict__ out, int n)
{
    __shared__ uint32_t As[128][36];
    __shared__ uint32_t Ws[32][136];
    const int tid = threadIdx.x;
    const int lane = tid & 31;
    const int wid = tid >> 5;
    const int wm = wid & 3;
    const int wn = wid >> 2;
    const int row0 = blockIdx.x * 128;
    const int lr = lane >> 2;
    const int lc = lane & 3;

    float acc[2][8][4];
#pragma unroll
    for (int mt = 0; mt < 2; mt++)
#pragma unroll
        for (int nt = 0; nt < 8; nt++)
#pragma unroll
            for (int j = 0; j < 4; j++) acc[mt][nt][j] = 0.f;

    const float4* A4 = (const float4*)A0;
    const float4* W4 = (const float4*)W0;
#pragma unroll
    for (int kc = 0; kc < 4; kc++) {
#pragma unroll
        for (int i = 0; i < 4; i++) {
            int idx = i * 256 + tid;
            int r = idx >> 3;
            int c4 = idx & 7;
            int row = row0 + r;
            float4 v = make_float4(0.f, 0.f, 0.f, 0.f);
            if (row < n) v = A4[(long long)row * 32 + kc * 8 + c4];
            As[r][c4 * 4 + 0] = f2tf(v.x);
            As[r][c4 * 4 + 1] = f2tf(v.y);
            As[r][c4 * 4 + 2] = f2tf(v.z);
            As[r][c4 * 4 + 3] = f2tf(v.w);
        }
#pragma unroll
        for (int i = 0; i < 4; i++) {
            int idx = i * 256 + tid;
            int r = idx >> 5;
            int c4 = idx & 31;
            float4 w = W4[(kc * 32 + r) * 32 + c4];
            Ws[r][c4 * 4 + 0] = f2tf(w.x);
            Ws[r][c4 * 4 + 1] = f2tf(w.y);
            Ws[r][c4 * 4 + 2] = f2tf(w.z);
            Ws[r][c4 * 4 + 3] = f2tf(w.w);
        }
        __syncthreads();
#pragma unroll
        for (int kk = 0; kk < 4; kk++) {
            int k0 = kk * 8;
            uint32_t a[2][4];
#pragma unroll
            for (int mt = 0; mt < 2; mt++) {
                int rb = wm * 32 + mt * 16;
                a[mt][0] = As[rb + lr][k0 + lc];
                a[mt][1] = As[rb + 8 + lr][k0 + lc];
                a[mt][2] = As[rb + lr][k0 + 4 + lc];
                a[mt][3] = As[rb + 8 + lr][k0 + 4 + lc];
            }
#pragma unroll
            for (int nt = 0; nt < 8; nt++) {
                int nb = wn * 64 + nt * 8;
                uint32_t b0 = Ws[k0 + lc][nb + lr];
                uint32_t b1 = Ws[k0 + 4 + lc][nb + lr];
                mma_tf32(acc[0][nt], a[0], b0, b1);
                mma_tf32(acc[1][nt], a[1], b0, b1);
            }
        }
        __syncthreads();
    }

#pragma unroll
    for (int nt = 0; nt < 8; nt++) {
        int cb = wn * 64 + nt * 8 + lc * 2;
#pragma unroll
        for (int mt = 0; mt < 2; mt++) {
            int r0 = row0 + wm * 32 + mt * 16 + lr;
#pragma unroll
            for (int h = 0; h < 2; h++) {
                int row = r0 + h * 8;
                if (row < n) {
                    float2 o = make_float2(acc[mt][nt][h * 2 + 0], acc[mt][nt][h * 2 + 1]);
                    *(float2*)&out[(long long)row * 128 + cb] = o;
                }
            }
        }
    }
}

// ---------------- gather-fused GCN layer GEMM ----------------
// For each 128-row tile: gather dir-O neighborhoods into smem A (fp32->tf32),
// MMA with 0.5*W_out; gather dir-I, MMA with 0.5*W_in; relu epilogue;
// POOL: reduce into pool1[batch] via smem pre-reduction, else write out.
template<bool POOL>
__global__ __launch_bounds__(512) void gemm_gcn(
    const float4* __restrict__ h4,
    const int* __restrict__ rowO, const int* __restrict__ degO,
    const int* __restrict__ nbrO, const float* __restrict__ coefO, const float* __restrict__ dsO,
    const int* __restrict__ rowI, const int* __restrict__ degI,
    const int* __restrict__ nbrI, const float* __restrict__ coefI, const float* __restrict__ dsI,
    const float* __restrict__ W0, const float* __restrict__ B0,   // out-dir weights
    const float* __restrict__ W1, const float* __restrict__ B1,   // in-dir weights
    const int* __restrict__ batch,
    float* __restrict__ outp, int n)
{
    extern __shared__ uint32_t smem[];
    uint32_t* As = smem;                    // [128][132]
    uint32_t* Ws = As + 128 * 132;          // [32][136]
    float* gpool = (float*)(Ws + 32 * 136); // [4][128]

    const int tid = threadIdx.x;
    const int lane = tid & 31;
    const int wid = tid >> 5;               // 0..15
    const int wm = wid & 7;                 // 8 warps along m (16 rows each)
    const int wn = wid >> 3;                // 2 warps along n (64 cols each)
    const int row0 = blockIdx.x * 128;
    const int lr = lane >> 2;
    const int lc = lane & 3;

    if (POOL && tid < 512) gpool[tid] = 0.f;

    float acc[8][4];
#pragma unroll
    for (int nt = 0; nt < 8; nt++)
#pragma unroll
        for (int j = 0; j < 4; j++) acc[nt][j] = 0.f;

#pragma unroll
    for (int p = 0; p < 2; p++) {
        const int* rp   = p ? rowI : rowO;
        const int* dg   = p ? degI : degO;
        const int* nbr  = p ? nbrI : nbrO;
        const float* cf = p ? coefI : coefO;
        const float* ds = p ? dsI : dsO;
        const float4* W4 = (const float4*)(p ? W1 : W0);

        // gather phase: 16 warps x 8 rows
        for (int rr = wid; rr < 128; rr += 16) {
            int node = row0 + rr;
            float4 a = make_float4(0.f, 0.f, 0.f, 0.f);
            if (node < n) {
                int beg = rp[node], cnt = dg[node];
                int i = 0;
                for (; i + 2 <= cnt; i += 2) {
                    int s0 = nbr[beg + i], s1 = nbr[beg + i + 1];
                    float c0 = cf[beg + i], c1 = cf[beg + i + 1];
                    float4 h0 = h4[(long long)s0 * 32 + lane];
                    float4 h1 = h4[(long long)s1 * 32 + lane];
                    a.x += c0 * h0.x + c1 * h1.x;
                    a.y += c0 * h0.y + c1 * h1.y;
                    a.z += c0 * h0.z + c1 * h1.z;
                    a.w += c0 * h0.w + c1 * h1.w;
                }
                if (i < cnt) {
                    int s0 = nbr[beg + i];
                    float c0 = cf[beg + i];
                    float4 h0 = h4[(long long)s0 * 32 + lane];
                    a.x += c0 * h0.x; a.y += c0 * h0.y;
                    a.z += c0 * h0.z; a.w += c0 * h0.w;
                }
                float dv = ds[node];
                a.x *= dv; a.y *= dv; a.z *= dv; a.w *= dv;
            }
            uint32_t* dr = As + rr * 132 + lane * 4;
            dr[0] = f2tf(a.x); dr[1] = f2tf(a.y);
            dr[2] = f2tf(a.z); dr[3] = f2tf(a.w);
        }
        __syncthreads();

        // MMA phase over 4 k-chunks
#pragma unroll
        for (int kc = 0; kc < 4; kc++) {
#pragma unroll
            for (int i = 0; i < 2; i++) {
                int idx = i * 512 + tid;
                int r = idx >> 5;
                int c4 = idx & 31;
                float4 w = W4[(kc * 32 + r) * 32 + c4];
                Ws[r * 136 + c4 * 4 + 0] = f2tf(0.5f * w.x);
                Ws[r * 136 + c4 * 4 + 1] = f2tf(0.5f * w.y);
                Ws[r * 136 + c4 * 4 + 2] = f2tf(0.5f * w.z);
                Ws[r * 136 + c4 * 4 + 3] = f2tf(0.5f * w.w);
            }
            __syncthreads();
#pragma unroll
            for (int kk = 0; kk < 4; kk++) {
                int k0 = kc * 32 + kk * 8;    // As col
                int kw = kk * 8;              // Ws row
                uint32_t a[4];
                int rb = wm * 16;
                a[0] = As[(rb + lr) * 132 + k0 + lc];
                a[1] = As[(rb + 8 + lr) * 132 + k0 + lc];
                a[2] = As[(rb + lr) * 132 + k0 + 4 + lc];
                a[3] = As[(rb + 8 + lr) * 132 + k0 + 4 + lc];
#pragma unroll
                for (int nt = 0; nt < 8; nt++) {
                    int nb = wn * 64 + nt * 8;
                    uint32_t b0 = Ws[(kw + lc) * 136 + nb + lr];
                    uint32_t b1 = Ws[(kw + 4 + lc) * 136 + nb + lr];
                    mma_tf32(acc[nt], a, b0, b1);
                }
            }
            __syncthreads();
        }
    }

    // epilogue
    int gmin = 0;
    if (POOL) gmin = batch[row0 < n ? row0 : (n - 1)];
#pragma unroll
    for (int nt = 0; nt < 8; nt++) {
        int cb = wn * 64 + nt * 8 + lc * 2;
        float bx = 0.5f * (B0[cb] + B1[cb]);
        float by = 0.5f * (B0[cb + 1] + B1[cb + 1]);
#pragma unroll
        for (int h = 0; h < 2; h++) {
            int row = row0 + wm * 16 + lr + h * 8;
            if (row < n) {
                float v0 = fmaxf(acc[nt][h * 2 + 0] + bx, 0.f);
                float v1 = fmaxf(acc[nt][h * 2 + 1] + by, 0.f);
                if (POOL) {
                    int g = batch[row];
                    unsigned gi = (unsigned)(g - gmin);
                    if (gi < 4u) {
                        atomicAdd(&gpool[gi * 128 + cb], v0);
                        atomicAdd(&gpool[gi * 128 + cb + 1], v1);
                    } else {
                        atomicAdd(&outp[g * 128 + cb], v0);
                        atomicAdd(&outp[g * 128 + cb + 1], v1);
                    }
                } else {
                    *(float2*)&outp[(long long)row * 128 + cb] = make_float2(v0, v1);
                }
            }
        }
    }
    if (POOL) {
        __syncthreads();
        if (tid < 512) {
            int gi = tid >> 7, col = tid & 127;
            int g = gmin + gi;
            if (g < GG) {
                float v = gpool[tid];
                if (v != 0.f) atomicAdd(&outp[g * 128 + col], v);
            }
        }
    }
}

// ---------------- fused GATv2 with pooled epilogue ----------------
__global__ __launch_bounds__(256) void gat_fused(
    const float4* __restrict__ gl4, const float4* __restrict__ gr4,
    const int* __restrict__ rowptr, const int* __restrict__ deg,
    const int* __restrict__ snode, const float* __restrict__ eav,
    const float* __restrict__ we, const float* __restrict__ attf,
    const int* __restrict__ batch,
    float* __restrict__ pool2, int nN)
{
    __shared__ float gp[2 * 128];
    int tid = threadIdx.x;
    int node = (blockIdx.x * blockDim.x + tid) >> 5;
    int lane = tid & 31;
    int node0 = blockIdx.x * (blockDim.x >> 5);
    gp[tid] = 0.f;   // 256 = 2*128
    __syncthreads();
    int gmin = batch[node0 < nN ? node0 : (nN - 1)];

    if (node < nN) {
        float4 r = gr4[(long long)node * 32 + lane];
        float4 w = ((const float4*)we)[lane];
        float4 at = ((const float4*)attf)[lane];
        int beg = rowptr[node], cnt = deg[node];
        float4 acc = make_float4(0.f, 0.f, 0.f, 0.f);
        float den = 0.f;
        for (int i = 0; i <= cnt; i++) {   // i == cnt -> self loop
            int s; float a;
            if (i < cnt) { s = snode[beg + i]; a = eav[beg + i]; }
            else         { s = node; a = 1.f; }
            float4 l = gl4[(long long)s * 32 + lane];
            float v0 = lrelu(l.x + r.x + a * w.x);
            float v1 = lrelu(l.y + r.y + a * w.y);
            float v2 = lrelu(l.z + r.z + a * w.z);
            float v3 = lrelu(l.w + r.w + a * w.w);
            float p = v0 * at.x + v1 * at.y + v2 * at.z + v3 * at.w;
            p += __shfl_xor_sync(0xFFFFFFFFu, p, 4);
            p += __shfl_xor_sync(0xFFFFFFFFu, p, 2);
            p += __shfl_xor_sync(0xFFFFFFFFu, p, 1);
            float ex = 0.f;
            if ((lane & 7) == 0) ex = __expf(p);
            ex = __shfl_sync(0xFFFFFFFFu, ex, lane & 24);
            den += ex;
            acc.x += ex * l.x; acc.y += ex * l.y;
            acc.z += ex * l.z; acc.w += ex * l.w;
        }
        float inv = 1.f / den;
        int g = batch[node];
        unsigned gi = (unsigned)(g - gmin);
        if (gi < 2u) {
            atomicAdd(&gp[gi * 128 + lane * 4 + 0], acc.x * inv);
            atomicAdd(&gp[gi * 128 + lane * 4 + 1], acc.y * inv);
            atomicAdd(&gp[gi * 128 + lane * 4 + 2], acc.z * inv);
            atomicAdd(&gp[gi * 128 + lane * 4 + 3], acc.w * inv);
        } else {
            red4(&pool2[g * 128 + lane * 4], acc.x * inv, acc.y * inv, acc.z * inv, acc.w * inv);
        }
    }
    __syncthreads();
    if (tid < 64) {
        int gi = tid >> 5, l = tid & 31;
        int g = gmin + gi;
        if (g < GG) {
            float* s = &gp[gi * 128 + l * 4];
            if (s[0] != 0.f || s[1] != 0.f || s[2] != 0.f || s[3] != 0.f)
                red4(&pool2[g * 128 + l * 4], s[0], s[1], s[2], s[3]);
        }
    }
}

// ---------------- finalize + head ----------------
__global__ void finalize_z(const float* __restrict__ pool1, const float* __restrict__ pool2,
                           const float* __restrict__ cnt, const float* __restrict__ gb,
                           float* __restrict__ z)
{
    int i = blockIdx.x * blockDim.x + threadIdx.x;
    if (i >= GG * 256) return;
    int g = i >> 8, j = i & 255;
    float c = fmaxf(cnt[g], 1.f);
    float v;
    if (j < 128) v = pool1[g * 128 + j] / c;
    else v = pool2[g * 128 + (j - 128)] / c + gb[j - 128];
    z[i] = v;
}

__global__ __launch_bounds__(128) void head_kernel(
    const float* __restrict__ z,
    const float* __restrict__ w1, const float* __restrict__ b1,
    const float* __restrict__ w2, const float* __restrict__ b2,
    float* __restrict__ out)
{
    __shared__ float zs[256];
    __shared__ float hid[128];
    int g = blockIdx.x;
    int tid = threadIdx.x;
    zs[tid] = z[g * 256 + tid];
    zs[tid + 128] = z[g * 256 + 128 + tid];
    __syncthreads();
    float acc = b1[tid];
#pragma unroll 8
    for (int k = 0; k < 256; k++) acc += zs[k] * w1[k * 128 + tid];
    hid[tid] = fmaxf(acc, 0.f);
    __syncthreads();
    if (tid < 2) {
        float s = b2[tid];
        for (int k = 0; k < 128; k++) s += hid[k] * w2[k * 2 + tid];
        out[g * 2 + tid] = s;
    }
}

// ---------------- launch ----------------
static inline int cdiv(long long a, long long b) { return (int)((a + b - 1) / b); }

#define FUSED_SMEM ((128 * 132 + 32 * 136 + 4 * 128) * 4)

extern "C" void kernel_launch(void* const* d_in, const int* in_sizes, int n_in,
                              void* d_out, int out_size)
{
    const float* x     = (const float*)d_in[0];
    const int*   ei    = (const int*)  d_in[1];
    const float* ea    = (const float*)d_in[2];
    const int*   batch = (const int*)  d_in[3];
    const float* dwin  = (const float*)d_in[4];
    const float* dbin  = (const float*)d_in[5];
    const float* dwout = (const float*)d_in[6];
    const float* dbout = (const float*)d_in[7];
    const float* gwl   = (const float*)d_in[8];
    const float* gwr   = (const float*)d_in[9];
    const float* gwe   = (const float*)d_in[10];
    const float* gatt  = (const float*)d_in[11];
    const float* gb    = (const float*)d_in[12];
    const float* w1    = (const float*)d_in[13];
    const float* b1    = (const float*)d_in[14];
    const float* w2    = (const float*)d_in[15];
    const float* b2    = (const float*)d_in[16];

    const int nN = in_sizes[0] / 128;
    const int nE = in_sizes[1] / 2;
    const int* src = ei;
    const int* dst = ei + nE;

    void *pA, *pGl, *pGr, *pdi, *pdo, *prI, *prO, *pcI, *pcO,
         *ppI, *ppO, *pid, *pis, *psn, *pci, *pea, *pdn, *pco, *pc, *pp1, *pp2, *pz;
    cudaGetSymbolAddress(&pA, g_bufA);
    cudaGetSymbolAddress(&pGl, g_gl);
    cudaGetSymbolAddress(&pGr, g_gr);
    cudaGetSymbolAddress(&pdi, g_degi);
    cudaGetSymbolAddress(&pdo, g_dego);
    cudaGetSymbolAddress(&prI, g_rowI);
    cudaGetSymbolAddress(&prO, g_rowO);
    cudaGetSymbolAddress(&pcI, g_curI);
    cudaGetSymbolAddress(&pcO, g_curO);
    cudaGetSymbolAddress(&ppI, g_partI);
    cudaGetSymbolAddress(&ppO, g_partO);
    cudaGetSymbolAddress(&pid, g_dinvd);
    cudaGetSymbolAddress(&pis, g_dinvs);
    cudaGetSymbolAddress(&psn, g_snode);
    cudaGetSymbolAddress(&pci, g_coefI);
    cudaGetSymbolAddress(&pea, g_eaI);
    cudaGetSymbolAddress(&pdn, g_dnode);
    cudaGetSymbolAddress(&pco, g_coefO);
    cudaGetSymbolAddress(&pc, g_cnt);
    cudaGetSymbolAddress(&pp1, g_pool1);
    cudaGetSymbolAddress(&pp2, g_pool2);
    cudaGetSymbolAddress(&pz, g_z);

    float* bufA  = (float*)pA;
    float* gl    = (float*)pGl;
    float* gr    = (float*)pGr;
    int*   degi  = (int*)pdi;
    int*   dego  = (int*)pdo;
    int*   rowI  = (int*)prI;
    int*   rowO  = (int*)prO;
    int*   curI  = (int*)pcI;
    int*   curO  = (int*)pcO;
    int*   partI = (int*)ppI;
    int*   partO = (int*)ppO;
    float* dinvd = (float*)pid;
    float* dinvs = (float*)pis;
    int*   snode = (int*)psn;
    float* coefI = (float*)pci;
    float* eaI   = (float*)pea;
    int*   dnode = (int*)pdn;
    float* coefO = (float*)pco;
    float* cnt   = (float*)pc;
    float* pool1 = (float*)pp1;
    float* pool2 = (float*)pp2;
    float* z     = (float*)pz;

    cudaFuncSetAttribute(gemm_gcn<false>, cudaFuncAttributeMaxDynamicSharedMemorySize, FUSED_SMEM);
    cudaFuncSetAttribute(gemm_gcn<true>,  cudaFuncAttributeMaxDynamicSharedMemorySize, FUSED_SMEM);

    const int T = 256;
    const int nb = cdiv(nN, SCAN_BLK);

    // 1-3: setup
    zero_misc<<<cdiv(nN, T), T>>>(degi, dego, cnt, pool1, pool2, nN);
    deg_kernel<<<cdiv(nE, T), T>>>(src, dst, degi, dego, nE);
    dinv_kernel<<<cdiv(nN, T), T>>>(degi, dego, dinvd, dinvs, batch, cnt, nN);

    // 4-5: GAT transforms (launch #4 gets profiled by ncu)
    gemm_tf32<<<cdiv(nN, 128), T>>>(x, gwl, gl, nN);
    gemm_tf32<<<cdiv(nN, 128), T>>>(x, gwr, gr, nN);

    // 6-9: CSR build
    scanA<<<dim3(nb, 2), SCAN_BLK>>>(degi, dego, rowI, rowO, partI, partO, nN);
    scanB<<<2, 128>>>(partI, partO, nb);
    scanC<<<dim3(nb, 2), SCAN_BLK>>>(rowI, rowO, partI, partO, curI, curO, nN);
    build_perm<<<cdiv(nE, T), T>>>(src, dst, ea, dinvd, dinvs, curI, curO,
                                   snode, coefI, eaI, dnode, coefO, nE);

    // 10: DirGNN layer 0 (fused gather+GEMM) -> bufA
    gemm_gcn<false><<<cdiv(nN, 128), 512, FUSED_SMEM>>>(
        (const float4*)x,
        rowO, dego, dnode, coefO, dinvs,
        rowI, degi, snode, coefI, dinvd,
        dwout, dbout, dwin, dbin, batch, bufA, nN);

    // 11: DirGNN layer 1 (fused gather+GEMM+pool) -> pool1
    gemm_gcn<true><<<cdiv(nN, 128), 512, FUSED_SMEM>>>(
        (const float4*)bufA,
        rowO, dego, dnode, coefO, dinvs,
        rowI, degi, snode, coefI, dinvd,
        dwout + 128 * 128, dbout + 128, dwin + 128 * 128, dbin + 128,
        batch, pool1, nN);

    // 12: fused GATv2 + pool -> pool2
    gat_fused<<<cdiv((long long)nN * 32, T), T>>>(
        (const float4*)gl, (const float4*)gr,
        rowI, degi, snode, eaI, gwe, gatt, batch, pool2, nN);

    // 13-14: finalize + head
    finalize_z<<<cdiv(GG * 256, T), T>>>(pool1, pool2, cnt, gb, z);
    head_kernel<<<GG, 128>>>(z, w1, b1, w2, b2, (float*)d_out);
}

// round 12
// speedup vs baseline: 1.0927x; 1.0927x over previous
#include <cuda_runtime.h>
#include <cuda_bf16.h>
#include <math.h>
#include <stdint.h>

// ---------------- problem constants ----------------
#define MAXN 100000
#define MAXE 1000000
#define GG 250
#define NEGSLOPE 0.2f
#define SCAN_BLK 1024
#define SCAN_NB ((MAXN + SCAN_BLK - 1) / SCAN_BLK)

// ---------------- static device scratch ----------------
__device__ float g_bufA[MAXN * 128];   // L0 out (L1 input)
__device__ float g_aggI[MAXN * 128];
__device__ float g_aggO[MAXN * 128];
__device__ float g_gl[MAXN * 128];
__device__ float g_gr[MAXN * 128];
__device__ int   g_degi[MAXN], g_dego[MAXN];
__device__ int   g_rowI[MAXN], g_rowO[MAXN];
__device__ int   g_curI[MAXN], g_curO[MAXN];
__device__ int   g_partI[SCAN_NB + 32], g_partO[SCAN_NB + 32];
__device__ float g_dinvd[MAXN], g_dinvs[MAXN];
__device__ int   g_snode[MAXE];
__device__ float g_coefI[MAXE];
__device__ float g_eaI[MAXE];
__device__ int   g_dnode[MAXE];
__device__ float g_coefO[MAXE];
__device__ float g_cnt[GG];
__device__ float g_pool1[GG * 128], g_pool2[GG * 128];
__device__ float g_z[GG * 256];

// ---------------- helpers ----------------
__device__ __forceinline__ void red4(float* p, float a, float b, float c, float d) {
    asm volatile("red.global.add.v4.f32 [%0], {%1,%2,%3,%4};"
                 :: "l"(p), "f"(a), "f"(b), "f"(c), "f"(d) : "memory");
}
__device__ __forceinline__ float lrelu(float x) {
    return (x > 0.f) ? x : NEGSLOPE * x;
}
__device__ __forceinline__ uint32_t f2tf(float f) {
    uint32_t u;
    asm("cvt.rna.tf32.f32 %0, %1;" : "=r"(u) : "f"(f));
    return u;
}
__device__ __forceinline__ void mma_tf32(float c[4], const uint32_t a[4], uint32_t b0, uint32_t b1) {
    asm volatile(
        "mma.sync.aligned.m16n8k8.row.col.f32.tf32.tf32.f32 "
        "{%0,%1,%2,%3}, {%4,%5,%6,%7}, {%8,%9}, {%0,%1,%2,%3};"
        : "+f"(c[0]), "+f"(c[1]), "+f"(c[2]), "+f"(c[3])
        : "r"(a[0]), "r"(a[1]), "r"(a[2]), "r"(a[3]), "r"(b0), "r"(b1));
}

// ---------------- setup kernels ----------------
__global__ void zero_misc(int* degi, int* dego, float* cnt,
                          float* pool1, float* pool2, int nN) {
    int i = blockIdx.x * blockDim.x + threadIdx.x;
    if (i < nN) { degi[i] = 0; dego[i] = 0; }
    if (i < GG) cnt[i] = 0.f;
    if (i < GG * 128) { pool1[i] = 0.f; pool2[i] = 0.f; }
}

__global__ void deg_kernel(const int* __restrict__ src, const int* __restrict__ dst,
                           int* degi, int* dego, int nE) {
    int e = blockIdx.x * blockDim.x + threadIdx.x;
    if (e >= nE) return;
    atomicAdd(&degi[dst[e]], 1);
    atomicAdd(&dego[src[e]], 1);
}

__global__ void dinv_kernel(const int* __restrict__ degi, const int* __restrict__ dego,
                            float* dd, float* ds,
                            const int* __restrict__ batch, float* cnt, int n) {
    int i = blockIdx.x * blockDim.x + threadIdx.x;
    if (i >= n) return;
    int a = degi[i], b = dego[i];
    dd[i] = (a > 0) ? rsqrtf((float)a) : 0.f;
    ds[i] = (b > 0) ? rsqrtf((float)b) : 0.f;
    atomicAdd(&cnt[batch[i]], 1.f);
}

// exclusive scan, phase A
__global__ __launch_bounds__(SCAN_BLK) void scanA(
    const int* __restrict__ degi, const int* __restrict__ dego,
    int* rowI, int* rowO, int* partI, int* partO, int n)
{
    const int* in = blockIdx.y ? dego : degi;
    int* out = blockIdx.y ? rowO : rowI;
    int* part = blockIdx.y ? partO : partI;
    int i = blockIdx.x * SCAN_BLK + threadIdx.x;
    int v = (i < n) ? in[i] : 0;
    int lane = threadIdx.x & 31, wid = threadIdx.x >> 5;
    int p = v;
#pragma unroll
    for (int o = 1; o < 32; o <<= 1) { int t = __shfl_up_sync(~0u, p, o); if (lane >= o) p += t; }
    __shared__ int ws[32];
    if (lane == 31) ws[wid] = p;
    __syncthreads();
    if (wid == 0) {
        int s = ws[lane];
#pragma unroll
        for (int o = 1; o < 32; o <<= 1) { int t = __shfl_up_sync(~0u, s, o); if (lane >= o) s += t; }
        ws[lane] = s;
    }
    __syncthreads();
    int base = wid ? ws[wid - 1] : 0;
    if (i < n) out[i] = base + p - v;
    if (threadIdx.x == SCAN_BLK - 1) part[blockIdx.x] = base + p;
}

__global__ __launch_bounds__(128) void scanB(int* partI, int* partO, int nb) {
    int* part = blockIdx.x ? partO : partI;
    int tid = threadIdx.x;
    int v = (tid < nb) ? part[tid] : 0;
    int lane = tid & 31, wid = tid >> 5;
    int p = v;
#pragma unroll
    for (int o = 1; o < 32; o <<= 1) { int t = __shfl_up_sync(~0u, p, o); if (lane >= o) p += t; }
    __shared__ int ws[4];
    if (lane == 31) ws[wid] = p;
    __syncthreads();
    int base = 0;
    for (int w = 0; w < wid; w++) base += ws[w];
    if (tid < nb) part[tid] = base + p - v;
}

__global__ __launch_bounds__(SCAN_BLK) void scanC(
    int* rowI, int* rowO, const int* __restrict__ partI, const int* __restrict__ partO,
    int* curI, int* curO, int n)
{
    int i = blockIdx.x * SCAN_BLK + threadIdx.x;
    if (i >= n) return;
    if (blockIdx.y == 0) { int r = rowI[i] + partI[blockIdx.x]; rowI[i] = r; curI[i] = r; }
    else                 { int r = rowO[i] + partO[blockIdx.x]; rowO[i] = r; curO[i] = r; }
}

__global__ __launch_bounds__(256) void build_perm(
    const int* __restrict__ src, const int* __restrict__ dst, const float* __restrict__ ea,
    const float* __restrict__ dinvd, const float* __restrict__ dinvs,
    int* curI, int* curO,
    int* snode, float* coefI, float* eaI,
    int* dnode, float* coefO, int nE)
{
    int e = blockIdx.x * blockDim.x + threadIdx.x;
    if (e >= nE) return;
    int s = src[e], d = dst[e];
    int pI = atomicAdd(&curI[d], 1);
    snode[pI] = s; coefI[pI] = dinvd[s]; eaI[pI] = ea[e];
    int pO = atomicAdd(&curO[s], 1);
    dnode[pO] = d; coefO[pO] = dinvs[d];
}

// ---------------- CSR gather: both directions via gridDim.y, unroll 4 ----------------
__global__ __launch_bounds__(256) void gather_both(
    const float4* __restrict__ h4,
    const int* __restrict__ rowO, const int* __restrict__ degO,
    const int* __restrict__ nbrO, const float* __restrict__ coefO, const float* __restrict__ dsO,
    const int* __restrict__ rowI, const int* __restrict__ degI,
    const int* __restrict__ nbrI, const float* __restrict__ coefI, const float* __restrict__ dsI,
    float4* __restrict__ aggO, float4* __restrict__ aggI, int nN)
{
    const int dir = blockIdx.y;
    const int* rp   = dir ? rowI : rowO;
    const int* dg   = dir ? degI : degO;
    const int* nbr  = dir ? nbrI : nbrO;
    const float* cf = dir ? coefI : coefO;
    const float* ds = dir ? dsI : dsO;
    float4* outb    = dir ? aggI : aggO;

    int t = blockIdx.x * blockDim.x + threadIdx.x;
    int node = t >> 5;
    int lane = t & 31;
    if (node >= nN) return;
    int beg = rp[node], cnt = dg[node];
    float4 acc = make_float4(0.f, 0.f, 0.f, 0.f);
    int i = 0;
    for (; i + 4 <= cnt; i += 4) {
        int s0 = nbr[beg + i], s1 = nbr[beg + i + 1];
        int s2 = nbr[beg + i + 2], s3 = nbr[beg + i + 3];
        float c0 = cf[beg + i], c1 = cf[beg + i + 1];
        float c2 = cf[beg + i + 2], c3 = cf[beg + i + 3];
        float4 h0 = h4[(long long)s0 * 32 + lane];
        float4 h1 = h4[(long long)s1 * 32 + lane];
        float4 h2 = h4[(long long)s2 * 32 + lane];
        float4 h3 = h4[(long long)s3 * 32 + lane];
        acc.x += c0 * h0.x + c1 * h1.x + c2 * h2.x + c3 * h3.x;
        acc.y += c0 * h0.y + c1 * h1.y + c2 * h2.y + c3 * h3.y;
        acc.z += c0 * h0.z + c1 * h1.z + c2 * h2.z + c3 * h3.z;
        acc.w += c0 * h0.w + c1 * h1.w + c2 * h2.w + c3 * h3.w;
    }
    for (; i < cnt; i++) {
        int s0 = nbr[beg + i];
        float c0 = cf[beg + i];
        float4 h0 = h4[(long long)s0 * 32 + lane];
        acc.x += c0 * h0.x; acc.y += c0 * h0.y;
        acc.z += c0 * h0.z; acc.w += c0 * h0.w;
    }
    float dv = ds[node];
    outb[(long long)node * 32 + lane] = make_float4(dv * acc.x, dv * acc.y, dv * acc.z, dv * acc.w);
}

// ---------------- dual-output TF32 GEMM: gl = x@Wl, gr = x@Wr (A staged once) ----------------
#define DUAL_SMEM ((128 * 132 + 32 * 136) * 4)
__global__ __launch_bounds__(256) void gemm_dual(
    const float* __restrict__ A0,
    const float* __restrict__ W0, const float* __restrict__ W1,
    float* __restrict__ out0, float* __restrict__ out1, int n)
{
    extern __shared__ uint32_t dsm[];
    uint32_t* As = dsm;               // [128][132]
    uint32_t* Ws = As + 128 * 132;    // [32][136]
    const int tid = threadIdx.x;
    const int lane = tid & 31;
    const int wid = tid >> 5;
    const int wm = wid & 3;
    const int wn = wid >> 2;
    const int row0 = blockIdx.x * 128;
    const int lr = lane >> 2;
    const int lc = lane & 3;

    const float4* A4 = (const float4*)A0;
    // stage full A tile once
#pragma unroll
    for (int i = 0; i < 16; i++) {
        int idx = i * 256 + tid;
        int r = idx >> 5;
        int c4 = idx & 31;
        int row = row0 + r;
        float4 v = make_float4(0.f, 0.f, 0.f, 0.f);
        if (row < n) v = A4[(long long)row * 32 + c4];
        uint32_t* dr = As + r * 132 + c4 * 4;
        dr[0] = f2tf(v.x); dr[1] = f2tf(v.y);
        dr[2] = f2tf(v.z); dr[3] = f2tf(v.w);
    }

#pragma unroll
    for (int p = 0; p < 2; p++) {
        const float4* W4 = (const float4*)(p ? W1 : W0);
        float* outp = p ? out1 : out0;
        float acc[2][8][4];
#pragma unroll
        for (int mt = 0; mt < 2; mt++)
#pragma unroll
            for (int nt = 0; nt < 8; nt++)
#pragma unroll
                for (int j = 0; j < 4; j++) acc[mt][nt][j] = 0.f;

#pragma unroll
        for (int kc = 0; kc < 4; kc++) {
            __syncthreads();
#pragma unroll
            for (int i = 0; i < 4; i++) {
                int idx = i * 256 + tid;
                int r = idx >> 5;
                int c4 = idx & 31;
                float4 w = W4[(kc * 32 + r) * 32 + c4];
                uint32_t* dr = Ws + r * 136 + c4 * 4;
                dr[0] = f2tf(w.x); dr[1] = f2tf(w.y);
                dr[2] = f2tf(w.z); dr[3] = f2tf(w.w);
            }
            __syncthreads();
#pragma unroll
            for (int kk = 0; kk < 4; kk++) {
                int k0 = kc * 32 + kk * 8;
                int kw = kk * 8;
                uint32_t a[2][4];
#pragma unroll
                for (int mt = 0; mt < 2; mt++) {
                    int rb = wm * 32 + mt * 16;
                    a[mt][0] = As[(rb + lr) * 132 + k0 + lc];
                    a[mt][1] = As[(rb + 8 + lr) * 132 + k0 + lc];
                    a[mt][2] = As[(rb + lr) * 132 + k0 + 4 + lc];
                    a[mt][3] = As[(rb + 8 + lr) * 132 + k0 + 4 + lc];
                }
#pragma unroll
                for (int nt = 0; nt < 8; nt++) {
                    int nb = wn * 64 + nt * 8;
                    uint32_t b0 = Ws[(kw + lc) * 136 + nb + lr];
                    uint32_t b1 = Ws[(kw + 4 + lc) * 136 + nb + lr];
                    mma_tf32(acc[0][nt], a[0], b0, b1);
                    mma_tf32(acc[1][nt], a[1], b0, b1);
                }
            }
        }
#pragma unroll
        for (int nt = 0; nt < 8; nt++) {
            int cb = wn * 64 + nt * 8 + lc * 2;
#pragma unroll
            for (int mt = 0; mt < 2; mt++) {
                int r0 = row0 + wm * 32 + mt * 16 + lr;
#pragma unroll
                for (int h = 0; h < 2; h++) {
                    int row = r0 + h * 8;
                    if (row < n) {
                        float2 o = make_float2(acc[mt][nt][h * 2 + 0], acc[mt][nt][h * 2 + 1]);
                        *(float2*)&outp[(long long)row * 128 + cb] = o;
                    }
                }
            }
        }
    }
}

// ---------------- pair TF32 GEMM (R8 style): out = 0.5*A0@W0 + 0.5*A1@W1 + bias, relu ----------------
// POOL: reduce rows into outp[batch[row]*128+col] (graph sums) instead of writing rows.
template<bool POOL>
__global__ __launch_bounds__(256) void gemm_pair(
    const float* __restrict__ A0, const float* __restrict__ W0, const float* __restrict__ B0,
    const float* __restrict__ A1, const float* __restrict__ W1, const float* __restrict__ B1,
    const int* __restrict__ batch,
    float* __restrict__ outp, int n)
{
    __shared__ uint32_t As[128][36];
    __shared__ uint32_t Ws[32][136];
    __shared__ float gpool[4 * 128];
    const int tid = threadIdx.x;
    const int lane = tid & 31;
    const int wid = tid >> 5;
    const int wm = wid & 3;
    const int wn = wid >> 2;
    const int row0 = blockIdx.x * 128;
    const int lr = lane >> 2;
    const int lc = lane & 3;

    if (POOL) { gpool[tid] = 0.f; gpool[tid + 256] = 0.f; }

    float acc[2][8][4];
#pragma unroll
    for (int mt = 0; mt < 2; mt++)
#pragma unroll
        for (int nt = 0; nt < 8; nt++)
#pragma unroll
            for (int j = 0; j < 4; j++) acc[mt][nt][j] = 0.f;

#pragma unroll
    for (int p = 0; p < 2; p++) {
        const float* A = (p == 0) ? A0 : A1;
        const float4* A4 = (const float4*)A;
        const float4* W4 = (const float4*)((p == 0) ? W0 : W1);
#pragma unroll
        for (int kc = 0; kc < 4; kc++) {
#pragma unroll
            for (int i = 0; i < 4; i++) {
                int idx = i * 256 + tid;
                int r = idx >> 3;
                int c4 = idx & 7;
                int row = row0 + r;
                float4 v = make_float4(0.f, 0.f, 0.f, 0.f);
                if (row < n) v = A4[(long long)row * 32 + kc * 8 + c4];
                As[r][c4 * 4 + 0] = f2tf(v.x);
                As[r][c4 * 4 + 1] = f2tf(v.y);
                As[r][c4 * 4 + 2] = f2tf(v.z);
                As[r][c4 * 4 + 3] = f2tf(v.w);
            }
#pragma unroll
            for (int i = 0; i < 4; i++) {
                int idx = i * 256 + tid;
                int r = idx >> 5;
                int c4 = idx & 31;
                float4 w = W4[(kc * 32 + r) * 32 + c4];
                Ws[r][c4 * 4 + 0] = f2tf(0.5f * w.x);
                Ws[r][c4 * 4 + 1] = f2tf(0.5f * w.y);
                Ws[r][c4 * 4 + 2] = f2tf(0.5f * w.z);
                Ws[r][c4 * 4 + 3] = f2tf(0.5f * w.w);
            }
            __syncthreads();
#pragma unroll
            for (int kk = 0; kk < 4; kk++) {
                int k0 = kk * 8;
                uint32_t a[2][4];
#pragma unroll
                for (int mt = 0; mt < 2; mt++) {
                    int rb = wm * 32 + mt * 16;
                    a[mt][0] = As[rb + lr][k0 + lc];
                    a[mt][1] = As[rb + 8 + lr][k0 + lc];
                    a[mt][2] = As[rb + lr][k0 + 4 + lc];
                    a[mt][3] = As[rb + 8 + lr][k0 + 4 + lc];
                }
#pragma unroll
                for (int nt = 0; nt < 8; nt++) {
                    int nb = wn * 64 + nt * 8;
                    uint32_t b0 = Ws[k0 + lc][nb + lr];
                    uint32_t b1 = Ws[k0 + 4 + lc][nb + lr];
                    mma_tf32(acc[0][nt], a[0], b0, b1);
                    mma_tf32(acc[1][nt], a[1], b0, b1);
                }
            }
            __syncthreads();
        }
    }

    int gmin = 0;
    if (POOL) gmin = batch[row0 < n ? row0 : (n - 1)];
#pragma unroll
    for (int nt = 0; nt < 8; nt++) {
        int cb = wn * 64 + nt * 8 + lc * 2;
        float bx = 0.5f * (B0[cb] + B1[cb]);
        float by = 0.5f * (B0[cb + 1] + B1[cb + 1]);
#pragma unroll
        for (int mt = 0; mt < 2; mt++) {
#pragma unroll
            for (int h = 0; h < 2; h++) {
                int row = row0 + wm * 32 + mt * 16 + lr + h * 8;
                if (row < n) {
                    float v0 = fmaxf(acc[mt][nt][h * 2 + 0] + bx, 0.f);
                    float v1 = fmaxf(acc[mt][nt][h * 2 + 1] + by, 0.f);
                    if (POOL) {
                        int g = batch[row];
                        unsigned gi = (unsigned)(g - gmin);
                        if (gi < 4u) {
                            atomicAdd(&gpool[gi * 128 + cb], v0);
                            atomicAdd(&gpool[gi * 128 + cb + 1], v1);
                        } else {
                            atomicAdd(&outp[g * 128 + cb], v0);
                            atomicAdd(&outp[g * 128 + cb + 1], v1);
                        }
                    } else {
                        *(float2*)&outp[(long long)row * 128 + cb] = make_float2(v0, v1);
                    }
                }
            }
        }
    }
    if (POOL) {
        __syncthreads();
#pragma unroll
        for (int i = 0; i < 2; i++) {
            int idx = i * 256 + tid;
            int gi = idx >> 7, col = idx & 127;
            int g = gmin + gi;
            if (g < GG) {
                float v = gpool[idx];
                if (v != 0.f) atomicAdd(&outp[g * 128 + col], v);
            }
        }
    }
}

// ---------------- fused GATv2 with pooled epilogue ----------------
__global__ __launch_bounds__(256) void gat_fused(
    const float4* __restrict__ gl4, const float4* __restrict__ gr4,
    const int* __restrict__ rowptr, const int* __restrict__ deg,
    const int* __restrict__ snode, const float* __restrict__ eav,
    const float* __restrict__ we, const float* __restrict__ attf,
    const int* __restrict__ batch,
    float* __restrict__ pool2, int nN)
{
    __shared__ float gp[2 * 128];
    int tid = threadIdx.x;
    int node = (blockIdx.x * blockDim.x + tid) >> 5;
    int lane = tid & 31;
    int node0 = blockIdx.x * (blockDim.x >> 5);
    gp[tid] = 0.f;
    __syncthreads();
    int gmin = batch[node0 < nN ? node0 : (nN - 1)];

    if (node < nN) {
        float4 r = gr4[(long long)node * 32 + lane];
        float4 w = ((const float4*)we)[lane];
        float4 at = ((const float4*)attf)[lane];
        int beg = rowptr[node], cnt = deg[node];
        float4 acc = make_float4(0.f, 0.f, 0.f, 0.f);
        float den = 0.f;
        for (int i = 0; i <= cnt; i++) {   // i == cnt -> self loop
            int s; float a;
            if (i < cnt) { s = snode[beg + i]; a = eav[beg + i]; }
            else         { s = node; a = 1.f; }
            float4 l = gl4[(long long)s * 32 + lane];
            float v0 = lrelu(l.x + r.x + a * w.x);
            float v1 = lrelu(l.y + r.y + a * w.y);
            float v2 = lrelu(l.z + r.z + a * w.z);
            float v3 = lrelu(l.w + r.w + a * w.w);
            float p = v0 * at.x + v1 * at.y + v2 * at.z + v3 * at.w;
            p += __shfl_xor_sync(0xFFFFFFFFu, p, 4);
            p += __shfl_xor_sync(0xFFFFFFFFu, p, 2);
            p += __shfl_xor_sync(0xFFFFFFFFu, p, 1);
            float ex = 0.f;
            if ((lane & 7) == 0) ex = __expf(p);
            ex = __shfl_sync(0xFFFFFFFFu, ex, lane & 24);
            den += ex;
            acc.x += ex * l.x; acc.y += ex * l.y;
            acc.z += ex * l.z; acc.w += ex * l.w;
        }
        float inv = 1.f / den;
        int g = batch[node];
        unsigned gi = (unsigned)(g - gmin);
        if (gi < 2u) {
            atomicAdd(&gp[gi * 128 + lane * 4 + 0], acc.x * inv);
            atomicAdd(&gp[gi * 128 + lane * 4 + 1], acc.y * inv);
            atomicAdd(&gp[gi * 128 + lane * 4 + 2], acc.z * inv);
            atomicAdd(&gp[gi * 128 + lane * 4 + 3], acc.w * inv);
        } else {
            red4(&pool2[g * 128 + lane * 4], acc.x * inv, acc.y * inv, acc.z * inv, acc.w * inv);
        }
    }
    __syncthreads();
    if (tid < 64) {
        int gi = tid >> 5, l = tid & 31;
        int g = gmin + gi;
        if (g < GG) {
            float* s = &gp[gi * 128 + l * 4];
            if (s[0] != 0.f || s[1] != 0.f || s[2] != 0.f || s[3] != 0.f)
                red4(&pool2[g * 128 + l * 4], s[0], s[1], s[2], s[3]);
        }
    }
}

// ---------------- finalize + head ----------------
__global__ void finalize_z(const float* __restrict__ pool1, const float* __restrict__ pool2,
                           const float* __restrict__ cnt, const float* __restrict__ gb,
                           float* __restrict__ z)
{
    int i = blockIdx.x * blockDim.x + threadIdx.x;
    if (i >= GG * 256) return;
    int g = i >> 8, j = i & 255;
    float c = fmaxf(cnt[g], 1.f);
    float v;
    if (j < 128) v = pool1[g * 128 + j] / c;
    else v = pool2[g * 128 + (j - 128)] / c + gb[j - 128];
    z[i] = v;
}

__global__ __launch_bounds__(128) void head_kernel(
    const float* __restrict__ z,
    const float* __restrict__ w1, const float* __restrict__ b1,
    const float* __restrict__ w2, const float* __restrict__ b2,
    float* __restrict__ out)
{
    __shared__ float zs[256];
    __shared__ float hid[128];
    int g = blockIdx.x;
    int tid = threadIdx.x;
    zs[tid] = z[g * 256 + tid];
    zs[tid + 128] = z[g * 256 + 128 + tid];
    __syncthreads();
    float acc = b1[tid];
#pragma unroll 8
    for (int k = 0; k < 256; k++) acc += zs[k] * w1[k * 128 + tid];
    hid[tid] = fmaxf(acc, 0.f);
    __syncthreads();
    if (tid < 2) {
        float s = b2[tid];
        for (int k = 0; k < 128; k++) s += hid[k] * w2[k * 2 + tid];
        out[g * 2 + tid] = s;
    }
}

// ---------------- launch ----------------
static inline int cdiv(long long a, long long b) { return (int)((a + b - 1) / b); }

extern "C" void kernel_launch(void* const* d_in, const int* in_sizes, int n_in,
                              void* d_out, int out_size)
{
    const float* x     = (const float*)d_in[0];
    const int*   ei    = (const int*)  d_in[1];
    const float* ea    = (const float*)d_in[2];
    const int*   batch = (const int*)  d_in[3];
    const float* dwin  = (const float*)d_in[4];
    const float* dbin  = (const float*)d_in[5];
    const float* dwout = (const float*)d_in[6];
    const float* dbout = (const float*)d_in[7];
    const float* gwl   = (const float*)d_in[8];
    const float* gwr   = (const float*)d_in[9];
    const float* gwe   = (const float*)d_in[10];
    const float* gatt  = (const float*)d_in[11];
    const float* gb    = (const float*)d_in[12];
    const float* w1    = (const float*)d_in[13];
    const float* b1    = (const float*)d_in[14];
    const float* w2    = (const float*)d_in[15];
    const float* b2    = (const float*)d_in[16];

    const int nN = in_sizes[0] / 128;
    const int nE = in_sizes[1] / 2;
    const int* src = ei;
    const int* dst = ei + nE;

    void *pA, *pI, *pO, *pGl, *pGr, *pdi, *pdo, *prI, *prO, *pcI, *pcO,
         *ppI, *ppO, *pid, *pis, *psn, *pci, *pea, *pdn, *pco, *pc, *pp1, *pp2, *pz;
    cudaGetSymbolAddress(&pA, g_bufA);
    cudaGetSymbolAddress(&pI, g_aggI);
    cudaGetSymbolAddress(&pO, g_aggO);
    cudaGetSymbolAddress(&pGl, g_gl);
    cudaGetSymbolAddress(&pGr, g_gr);
    cudaGetSymbolAddress(&pdi, g_degi);
    cudaGetSymbolAddress(&pdo, g_dego);
    cudaGetSymbolAddress(&prI, g_rowI);
    cudaGetSymbolAddress(&prO, g_rowO);
    cudaGetSymbolAddress(&pcI, g_curI);
    cudaGetSymbolAddress(&pcO, g_curO);
    cudaGetSymbolAddress(&ppI, g_partI);
    cudaGetSymbolAddress(&ppO, g_partO);
    cudaGetSymbolAddress(&pid, g_dinvd);
    cudaGetSymbolAddress(&pis, g_dinvs);
    cudaGetSymbolAddress(&psn, g_snode);
    cudaGetSymbolAddress(&pci, g_coefI);
    cudaGetSymbolAddress(&pea, g_eaI);
    cudaGetSymbolAddress(&pdn, g_dnode);
    cudaGetSymbolAddress(&pco, g_coefO);
    cudaGetSymbolAddress(&pc, g_cnt);
    cudaGetSymbolAddress(&pp1, g_pool1);
    cudaGetSymbolAddress(&pp2, g_pool2);
    cudaGetSymbolAddress(&pz, g_z);

    float* bufA  = (float*)pA;
    float* aggI  = (float*)pI;
    float* aggO  = (float*)pO;
    float* gl    = (float*)pGl;
    float* gr    = (float*)pGr;
    int*   degi  = (int*)pdi;
    int*   dego  = (int*)pdo;
    int*   rowI  = (int*)prI;
    int*   rowO  = (int*)prO;
    int*   curI  = (int*)pcI;
    int*   curO  = (int*)pcO;
    int*   partI = (int*)ppI;
    int*   partO = (int*)ppO;
    float* dinvd = (float*)pid;
    float* dinvs = (float*)pis;
    int*   snode = (int*)psn;
    float* coefI = (float*)pci;
    float* eaI   = (float*)pea;
    int*   dnode = (int*)pdn;
    float* coefO = (float*)pco;
    float* cnt   = (float*)pc;
    float* pool1 = (float*)pp1;
    float* pool2 = (float*)pp2;
    float* z     = (float*)pz;

    cudaFuncSetAttribute(gemm_dual, cudaFuncAttributeMaxDynamicSharedMemorySize, DUAL_SMEM);

    const int T = 256;
    const int nb = cdiv(nN, SCAN_BLK);
    const int gatherBlocks = cdiv((long long)nN * 32, T);

    // 1-3: setup
    zero_misc<<<cdiv(nN, T), T>>>(degi, dego, cnt, pool1, pool2, nN);
    deg_kernel<<<cdiv(nE, T), T>>>(src, dst, degi, dego, nE);
    dinv_kernel<<<cdiv(nN, T), T>>>(degi, dego, dinvd, dinvs, batch, cnt, nN);

    // 4: dual GAT transform (profiled by ncu)
    gemm_dual<<<cdiv(nN, 128), T, DUAL_SMEM>>>(x, gwl, gwr, gl, gr, nN);

    // 5-8: CSR build
    scanA<<<dim3(nb, 2), SCAN_BLK>>>(degi, dego, rowI, rowO, partI, partO, nN);
    scanB<<<2, 128>>>(partI, partO, nb);
    scanC<<<dim3(nb, 2), SCAN_BLK>>>(rowI, rowO, partI, partO, curI, curO, nN);
    build_perm<<<cdiv(nE, T), T>>>(src, dst, ea, dinvd, dinvs, curI, curO,
                                   snode, coefI, eaI, dnode, coefO, nE);

    // 9-10: DirGNN layer 0
    gather_both<<<dim3(gatherBlocks, 2), T>>>((const float4*)x,
        rowO, dego, dnode, coefO, dinvs,
        rowI, degi, snode, coefI, dinvd,
        (float4*)aggO, (float4*)aggI, nN);
    gemm_pair<false><<<cdiv(nN, 128), T>>>(aggO, dwout, dbout,
                                           aggI, dwin, dbin, batch, bufA, nN);

    // 11-12: DirGNN layer 1 (pooled epilogue -> pool1)
    gather_both<<<dim3(gatherBlocks, 2), T>>>((const float4*)bufA,
        rowO, dego, dnode, coefO, dinvs,
        rowI, degi, snode, coefI, dinvd,
        (float4*)aggO, (float4*)aggI, nN);
    gemm_pair<true><<<cdiv(nN, 128), T>>>(aggO, dwout + 128 * 128, dbout + 128,
                                          aggI, dwin + 128 * 128, dbin + 128,
                                          batch, pool1, nN);

    // 13: fused GATv2 + pool -> pool2
    gat_fused<<<gatherBlocks, T>>>(
        (const float4*)gl, (const float4*)gr,
        rowI, degi, snode, eaI, gwe, gatt, batch, pool2, nN);

    // 14-15: finalize + head
    finalize_z<<<cdiv(GG * 256, T), T>>>(pool1, pool2, cnt, gb, z);
    head_kernel<<<GG, 128>>>(z, w1, b1, w2, b2, (float*)d_out);
}

// round 14
// speedup vs baseline: 1.3920x; 1.2740x over previous
#include <cuda_runtime.h>
#include <cuda_fp16.h>
#include <math.h>
#include <stdint.h>

// ---------------- problem constants ----------------
#define MAXN 100000
#define MAXE 1000000
#define GG 250
#define NEGSLOPE 0.2f
#define SCAN_BLK 1024
#define SCAN_NB ((MAXN + SCAN_BLK - 1) / SCAN_BLK)

// ---------------- static device scratch ----------------
__device__ __half g_xh[MAXN * 128];    // fp16 copy of x
__device__ __half g_bufAh[MAXN * 128]; // L0 out (fp16, gather input for L1)
__device__ __half g_glh[MAXN * 128];   // GAT left transform (fp16)
__device__ __half g_grh[MAXN * 128];   // GAT right transform (fp16)
__device__ float g_bufB[MAXN * 128];   // L1 out (fp32, pooled later)
__device__ float g_aggI[MAXN * 128];   // fp32 agg -> also reused as out2
__device__ float g_aggO[MAXN * 128];
__device__ int   g_degi[MAXN], g_dego[MAXN];
__device__ int   g_rowI[MAXN], g_rowO[MAXN];
__device__ int   g_curI[MAXN], g_curO[MAXN];
__device__ int   g_partI[SCAN_NB + 32], g_partO[SCAN_NB + 32];
__device__ float g_dinvd[MAXN], g_dinvs[MAXN];
__device__ int   g_snode[MAXE];
__device__ float g_coefI[MAXE];
__device__ float g_eaI[MAXE];
__device__ int   g_dnode[MAXE];
__device__ float g_coefO[MAXE];
__device__ float g_cnt[GG];
__device__ float g_pool1[GG * 128], g_pool2[GG * 128];
__device__ float g_z[GG * 256];

// ---------------- helpers ----------------
__device__ __forceinline__ void red4(float* p, float a, float b, float c, float d) {
    asm volatile("red.global.add.v4.f32 [%0], {%1,%2,%3,%4};"
                 :: "l"(p), "f"(a), "f"(b), "f"(c), "f"(d) : "memory");
}
__device__ __forceinline__ float lrelu(float x) {
    return (x > 0.f) ? x : NEGSLOPE * x;
}
__device__ __forceinline__ uint32_t f2tf(float f) {
    uint32_t u;
    asm("cvt.rna.tf32.f32 %0, %1;" : "=r"(u) : "f"(f));
    return u;
}
__device__ __forceinline__ void mma_tf32(float c[4], const uint32_t a[4], uint32_t b0, uint32_t b1) {
    asm volatile(
        "mma.sync.aligned.m16n8k8.row.col.f32.tf32.tf32.f32 "
        "{%0,%1,%2,%3}, {%4,%5,%6,%7}, {%8,%9}, {%0,%1,%2,%3};"
        : "+f"(c[0]), "+f"(c[1]), "+f"(c[2]), "+f"(c[3])
        : "r"(a[0]), "r"(a[1]), "r"(a[2]), "r"(a[3]), "r"(b0), "r"(b1));
}
// load 4 consecutive fp16 cols (lane-mapped like float4) and widen to fp32
__device__ __forceinline__ float4 ld_h4(const uint2* __restrict__ base, long long idx) {
    uint2 u = __ldg(&base[idx]);
    __half2 p0 = *(__half2*)&u.x;
    __half2 p1 = *(__half2*)&u.y;
    float2 f0 = __half22float2(p0);
    float2 f1 = __half22float2(p1);
    return make_float4(f0.x, f0.y, f1.x, f1.y);
}

// ---------------- setup kernels ----------------
__global__ void zero_misc(int* degi, int* dego, float* cnt,
                          float* pool1, float* pool2, int nN) {
    int i = blockIdx.x * blockDim.x + threadIdx.x;
    if (i < nN) { degi[i] = 0; dego[i] = 0; }
    if (i < GG) cnt[i] = 0.f;
    if (i < GG * 128) { pool1[i] = 0.f; pool2[i] = 0.f; }
}

__global__ void deg_kernel(const int* __restrict__ src, const int* __restrict__ dst,
                           int* degi, int* dego, int nE) {
    int e = blockIdx.x * blockDim.x + threadIdx.x;
    if (e >= nE) return;
    atomicAdd(&degi[dst[e]], 1);
    atomicAdd(&dego[src[e]], 1);
}

__global__ void dinv_kernel(const int* __restrict__ degi, const int* __restrict__ dego,
                            float* dd, float* ds,
                            const int* __restrict__ batch, float* cnt, int n) {
    int i = blockIdx.x * blockDim.x + threadIdx.x;
    if (i >= n) return;
    int a = degi[i], b = dego[i];
    dd[i] = (a > 0) ? rsqrtf((float)a) : 0.f;
    ds[i] = (b > 0) ? rsqrtf((float)b) : 0.f;
    atomicAdd(&cnt[batch[i]], 1.f);
}

// x (fp32) -> fp16 copy
__global__ void cvt_x(const float2* __restrict__ xf2, __half2* __restrict__ xh, long long n2) {
    long long i = (long long)blockIdx.x * blockDim.x + threadIdx.x;
    if (i < n2) xh[i] = __float22half2_rn(xf2[i]);
}

// exclusive scan, phase A
__global__ __launch_bounds__(SCAN_BLK) void scanA(
    const int* __restrict__ degi, const int* __restrict__ dego,
    int* rowI, int* rowO, int* partI, int* partO, int n)
{
    const int* in = blockIdx.y ? dego : degi;
    int* out = blockIdx.y ? rowO : rowI;
    int* part = blockIdx.y ? partO : partI;
    int i = blockIdx.x * SCAN_BLK + threadIdx.x;
    int v = (i < n) ? in[i] : 0;
    int lane = threadIdx.x & 31, wid = threadIdx.x >> 5;
    int p = v;
#pragma unroll
    for (int o = 1; o < 32; o <<= 1) { int t = __shfl_up_sync(~0u, p, o); if (lane >= o) p += t; }
    __shared__ int ws[32];
    if (lane == 31) ws[wid] = p;
    __syncthreads();
    if (wid == 0) {
        int s = ws[lane];
#pragma unroll
        for (int o = 1; o < 32; o <<= 1) { int t = __shfl_up_sync(~0u, s, o); if (lane >= o) s += t; }
        ws[lane] = s;
    }
    __syncthreads();
    int base = wid ? ws[wid - 1] : 0;
    if (i < n) out[i] = base + p - v;
    if (threadIdx.x == SCAN_BLK - 1) part[blockIdx.x] = base + p;
}

__global__ __launch_bounds__(128) void scanB(int* partI, int* partO, int nb) {
    int* part = blockIdx.x ? partO : partI;
    int tid = threadIdx.x;
    int v = (tid < nb) ? part[tid] : 0;
    int lane = tid & 31, wid = tid >> 5;
    int p = v;
#pragma unroll
    for (int o = 1; o < 32; o <<= 1) { int t = __shfl_up_sync(~0u, p, o); if (lane >= o) p += t; }
    __shared__ int ws[4];
    if (lane == 31) ws[wid] = p;
    __syncthreads();
    int base = 0;
    for (int w = 0; w < wid; w++) base += ws[w];
    if (tid < nb) part[tid] = base + p - v;
}

__global__ __launch_bounds__(SCAN_BLK) void scanC(
    int* rowI, int* rowO, const int* __restrict__ partI, const int* __restrict__ partO,
    int* curI, int* curO, int n)
{
    int i = blockIdx.x * SCAN_BLK + threadIdx.x;
    if (i >= n) return;
    if (blockIdx.y == 0) { int r = rowI[i] + partI[blockIdx.x]; rowI[i] = r; curI[i] = r; }
    else                 { int r = rowO[i] + partO[blockIdx.x]; rowO[i] = r; curO[i] = r; }
}

__global__ __launch_bounds__(256) void build_perm(
    const int* __restrict__ src, const int* __restrict__ dst, const float* __restrict__ ea,
    const float* __restrict__ dinvd, const float* __restrict__ dinvs,
    int* curI, int* curO,
    int* snode, float* coefI, float* eaI,
    int* dnode, float* coefO, int nE)
{
    int e = blockIdx.x * blockDim.x + threadIdx.x;
    if (e >= nE) return;
    int s = src[e], d = dst[e];
    int pI = atomicAdd(&curI[d], 1);
    snode[pI] = s; coefI[pI] = dinvd[s]; eaI[pI] = ea[e];
    int pO = atomicAdd(&curO[s], 1);
    dnode[pO] = d; coefO[pO] = dinvs[d];
}

// ---------------- GCN CSR gather (fp16 features, fp32 accumulate), warp/node ----------------
__global__ __launch_bounds__(256) void gcn_gather(
    const uint2* __restrict__ h2,   // fp16 rows: 32 x uint2 per row
    const int* __restrict__ rowptr, const int* __restrict__ deg,
    const int* __restrict__ nbr, const float* __restrict__ coef,
    const float* __restrict__ dself,
    float4* __restrict__ outb, int nN)
{
    int t = blockIdx.x * blockDim.x + threadIdx.x;
    int node = t >> 5;
    int lane = t & 31;
    if (node >= nN) return;
    int beg = rowptr[node], cnt = deg[node];
    float4 acc = make_float4(0.f, 0.f, 0.f, 0.f);
    int i = 0;
    for (; i + 2 <= cnt; i += 2) {
        int s0 = nbr[beg + i], s1 = nbr[beg + i + 1];
        float c0 = coef[beg + i], c1 = coef[beg + i + 1];
        float4 h0 = ld_h4(h2, (long long)s0 * 32 + lane);
        float4 h1 = ld_h4(h2, (long long)s1 * 32 + lane);
        acc.x += c0 * h0.x + c1 * h1.x;
        acc.y += c0 * h0.y + c1 * h1.y;
        acc.z += c0 * h0.z + c1 * h1.z;
        acc.w += c0 * h0.w + c1 * h1.w;
    }
    if (i < cnt) {
        int s0 = nbr[beg + i];
        float c0 = coef[beg + i];
        float4 h0 = ld_h4(h2, (long long)s0 * 32 + lane);
        acc.x += c0 * h0.x; acc.y += c0 * h0.y;
        acc.z += c0 * h0.z; acc.w += c0 * h0.w;
    }
    float dv = dself[node];
    outb[(long long)node * 32 + lane] = make_float4(dv * acc.x, dv * acc.y, dv * acc.z, dv * acc.w);
}

// ---------------- dual-output TF32 GEMM: gl = x@Wl, gr = x@Wr (fp16 outputs) ----------------
#define DUAL_SMEM ((128 * 132 + 32 * 136) * 4)
__global__ __launch_bounds__(256) void gemm_dual(
    const float* __restrict__ A0,
    const float* __restrict__ W0, const float* __restrict__ W1,
    __half* __restrict__ out0, __half* __restrict__ out1, int n)
{
    extern __shared__ uint32_t dsm[];
    uint32_t* As = dsm;               // [128][132]
    uint32_t* Ws = As + 128 * 132;    // [32][136]
    const int tid = threadIdx.x;
    const int lane = tid & 31;
    const int wid = tid >> 5;
    const int wm = wid & 3;
    const int wn = wid >> 2;
    const int row0 = blockIdx.x * 128;
    const int lr = lane >> 2;
    const int lc = lane & 3;

    const float4* A4 = (const float4*)A0;
#pragma unroll
    for (int i = 0; i < 16; i++) {
        int idx = i * 256 + tid;
        int r = idx >> 5;
        int c4 = idx & 31;
        int row = row0 + r;
        float4 v = make_float4(0.f, 0.f, 0.f, 0.f);
        if (row < n) v = A4[(long long)row * 32 + c4];
        uint32_t* dr = As + r * 132 + c4 * 4;
        dr[0] = f2tf(v.x); dr[1] = f2tf(v.y);
        dr[2] = f2tf(v.z); dr[3] = f2tf(v.w);
    }

#pragma unroll
    for (int p = 0; p < 2; p++) {
        const float4* W4 = (const float4*)(p ? W1 : W0);
        __half* outp = p ? out1 : out0;
        float acc[2][8][4];
#pragma unroll
        for (int mt = 0; mt < 2; mt++)
#pragma unroll
            for (int nt = 0; nt < 8; nt++)
#pragma unroll
                for (int j = 0; j < 4; j++) acc[mt][nt][j] = 0.f;

#pragma unroll
        for (int kc = 0; kc < 4; kc++) {
            __syncthreads();
#pragma unroll
            for (int i = 0; i < 4; i++) {
                int idx = i * 256 + tid;
                int r = idx >> 5;
                int c4 = idx & 31;
                float4 w = W4[(kc * 32 + r) * 32 + c4];
                uint32_t* dr = Ws + r * 136 + c4 * 4;
                dr[0] = f2tf(w.x); dr[1] = f2tf(w.y);
                dr[2] = f2tf(w.z); dr[3] = f2tf(w.w);
            }
            __syncthreads();
#pragma unroll
            for (int kk = 0; kk < 4; kk++) {
                int k0 = kc * 32 + kk * 8;
                int kw = kk * 8;
                uint32_t a[2][4];
#pragma unroll
                for (int mt = 0; mt < 2; mt++) {
                    int rb = wm * 32 + mt * 16;
                    a[mt][0] = As[(rb + lr) * 132 + k0 + lc];
                    a[mt][1] = As[(rb + 8 + lr) * 132 + k0 + lc];
                    a[mt][2] = As[(rb + lr) * 132 + k0 + 4 + lc];
                    a[mt][3] = As[(rb + 8 + lr) * 132 + k0 + 4 + lc];
                }
#pragma unroll
                for (int nt = 0; nt < 8; nt++) {
                    int nb = wn * 64 + nt * 8;
                    uint32_t b0 = Ws[(kw + lc) * 136 + nb + lr];
                    uint32_t b1 = Ws[(kw + 4 + lc) * 136 + nb + lr];
                    mma_tf32(acc[0][nt], a[0], b0, b1);
                    mma_tf32(acc[1][nt], a[1], b0, b1);
                }
            }
        }
#pragma unroll
        for (int nt = 0; nt < 8; nt++) {
            int cb = wn * 64 + nt * 8 + lc * 2;
#pragma unroll
            for (int mt = 0; mt < 2; mt++) {
                int r0 = row0 + wm * 32 + mt * 16 + lr;
#pragma unroll
                for (int h = 0; h < 2; h++) {
                    int row = r0 + h * 8;
                    if (row < n) {
                        float2 o = make_float2(acc[mt][nt][h * 2 + 0], acc[mt][nt][h * 2 + 1]);
                        ((__half2*)outp)[(long long)row * 64 + (cb >> 1)] = __float22half2_rn(o);
                    }
                }
            }
        }
    }
}

// ---------------- pair TF32 GEMM: out = relu(0.5*A0@W0 + 0.5*A1@W1 + bias) ----------------
// H16OUT: write fp16 rows (L0, feeds next gather); else fp32 rows (L1, feeds pool).
template<bool H16OUT>
__global__ __launch_bounds__(256) void gemm_pair(
    const float* __restrict__ A0, const float* __restrict__ W0, const float* __restrict__ B0,
    const float* __restrict__ A1, const float* __restrict__ W1, const float* __restrict__ B1,
    void* __restrict__ outp, int n)
{
    __shared__ uint32_t As[128][36];
    __shared__ uint32_t Ws[32][136];
    const int tid = threadIdx.x;
    const int lane = tid & 31;
    const int wid = tid >> 5;
    const int wm = wid & 3;
    const int wn = wid >> 2;
    const int row0 = blockIdx.x * 128;
    const int lr = lane >> 2;
    const int lc = lane & 3;

    float acc[2][8][4];
#pragma unroll
    for (int mt = 0; mt < 2; mt++)
#pragma unroll
        for (int nt = 0; nt < 8; nt++)
#pragma unroll
            for (int j = 0; j < 4; j++) acc[mt][nt][j] = 0.f;

#pragma unroll
    for (int p = 0; p < 2; p++) {
        const float4* A4 = (const float4*)((p == 0) ? A0 : A1);
        const float4* W4 = (const float4*)((p == 0) ? W0 : W1);
#pragma unroll
        for (int kc = 0; kc < 4; kc++) {
#pragma unroll
            for (int i = 0; i < 4; i++) {
                int idx = i * 256 + tid;
                int r = idx >> 3;
                int c4 = idx & 7;
                int row = row0 + r;
                float4 v = make_float4(0.f, 0.f, 0.f, 0.f);
                if (row < n) v = A4[(long long)row * 32 + kc * 8 + c4];
                As[r][c4 * 4 + 0] = f2tf(v.x);
                As[r][c4 * 4 + 1] = f2tf(v.y);
                As[r][c4 * 4 + 2] = f2tf(v.z);
                As[r][c4 * 4 + 3] = f2tf(v.w);
            }
#pragma unroll
            for (int i = 0; i < 4; i++) {
                int idx = i * 256 + tid;
                int r = idx >> 5;
                int c4 = idx & 31;
                float4 w = W4[(kc * 32 + r) * 32 + c4];
                Ws[r][c4 * 4 + 0] = f2tf(0.5f * w.x);
                Ws[r][c4 * 4 + 1] = f2tf(0.5f * w.y);
                Ws[r][c4 * 4 + 2] = f2tf(0.5f * w.z);
                Ws[r][c4 * 4 + 3] = f2tf(0.5f * w.w);
            }
            __syncthreads();
#pragma unroll
            for (int kk = 0; kk < 4; kk++) {
                int k0 = kk * 8;
                uint32_t a[2][4];
#pragma unroll
                for (int mt = 0; mt < 2; mt++) {
                    int rb = wm * 32 + mt * 16;
                    a[mt][0] = As[rb + lr][k0 + lc];
                    a[mt][1] = As[rb + 8 + lr][k0 + lc];
                    a[mt][2] = As[rb + lr][k0 + 4 + lc];
                    a[mt][3] = As[rb + 8 + lr][k0 + 4 + lc];
                }
#pragma unroll
                for (int nt = 0; nt < 8; nt++) {
                    int nb = wn * 64 + nt * 8;
                    uint32_t b0 = Ws[k0 + lc][nb + lr];
                    uint32_t b1 = Ws[k0 + 4 + lc][nb + lr];
                    mma_tf32(acc[0][nt], a[0], b0, b1);
                    mma_tf32(acc[1][nt], a[1], b0, b1);
                }
            }
            __syncthreads();
        }
    }

#pragma unroll
    for (int nt = 0; nt < 8; nt++) {
        int cb = wn * 64 + nt * 8 + lc * 2;
        float bx = 0.5f * (B0[cb] + B1[cb]);
        float by = 0.5f * (B0[cb + 1] + B1[cb + 1]);
#pragma unroll
        for (int mt = 0; mt < 2; mt++) {
#pragma unroll
            for (int h = 0; h < 2; h++) {
                int row = row0 + wm * 32 + mt * 16 + lr + h * 8;
                if (row < n) {
                    float v0 = fmaxf(acc[mt][nt][h * 2 + 0] + bx, 0.f);
                    float v1 = fmaxf(acc[mt][nt][h * 2 + 1] + by, 0.f);
                    if (H16OUT) {
                        ((__half2*)outp)[(long long)row * 64 + (cb >> 1)] =
                            __float22half2_rn(make_float2(v0, v1));
                    } else {
                        *(float2*)&((float*)outp)[(long long)row * 128 + cb] = make_float2(v0, v1);
                    }
                }
            }
        }
    }
}

// ---------------- fused GATv2: single gather pass per node (fp16 gl/gr) ----------------
__global__ __launch_bounds__(256) void gat_fused(
    const uint2* __restrict__ gl2, const uint2* __restrict__ gr2,
    const int* __restrict__ rowptr, const int* __restrict__ deg,
    const int* __restrict__ snode, const float* __restrict__ eav,
    const float* __restrict__ we, const float* __restrict__ attf,
    float4* __restrict__ out2, int nN)
{
    int t = blockIdx.x * blockDim.x + threadIdx.x;
    int node = t >> 5;
    int lane = t & 31;
    if (node >= nN) return;
    float4 r = ld_h4(gr2, (long long)node * 32 + lane);
    float4 w = ((const float4*)we)[lane];
    float4 at = ((const float4*)attf)[lane];
    int beg = rowptr[node], cnt = deg[node];
    float4 acc = make_float4(0.f, 0.f, 0.f, 0.f);
    float den = 0.f;
    for (int i = 0; i <= cnt; i++) {   // i == cnt -> self loop
        int s; float a;
        if (i < cnt) { s = snode[beg + i]; a = eav[beg + i]; }
        else         { s = node; a = 1.f; }
        float4 l = ld_h4(gl2, (long long)s * 32 + lane);
        float v0 = lrelu(l.x + r.x + a * w.x);
        float v1 = lrelu(l.y + r.y + a * w.y);
        float v2 = lrelu(l.z + r.z + a * w.z);
        float v3 = lrelu(l.w + r.w + a * w.w);
        float p = v0 * at.x + v1 * at.y + v2 * at.z + v3 * at.w;
        p += __shfl_xor_sync(0xFFFFFFFFu, p, 4);
        p += __shfl_xor_sync(0xFFFFFFFFu, p, 2);
        p += __shfl_xor_sync(0xFFFFFFFFu, p, 1);
        float ex = 0.f;
        if ((lane & 7) == 0) ex = __expf(p);
        ex = __shfl_sync(0xFFFFFFFFu, ex, lane & 24);
        den += ex;
        acc.x += ex * l.x; acc.y += ex * l.y;
        acc.z += ex * l.z; acc.w += ex * l.w;
    }
    float inv = 1.f / den;
    out2[(long long)node * 32 + lane] =
        make_float4(acc.x * inv, acc.y * inv, acc.z * inv, acc.w * inv);
}

// ---------------- mean pool (sums; counts done in dinv_kernel) ----------------
__global__ __launch_bounds__(256) void pool_kernel(
    const float4* __restrict__ h4, const float4* __restrict__ o4,
    const int* __restrict__ batch,
    float* __restrict__ pool1, float* __restrict__ pool2, int n)
{
    int t = blockIdx.x * blockDim.x + threadIdx.x;
    int node = t >> 5;
    int lane = t & 31;
    if (node >= n) return;
    int g = batch[node];
    float4 hv = h4[(long long)node * 32 + lane];
    red4(&pool1[g * 128 + lane * 4], hv.x, hv.y, hv.z, hv.w);
    float4 ov = o4[(long long)node * 32 + lane];
    red4(&pool2[g * 128 + lane * 4], ov.x, ov.y, ov.z, ov.w);
}

// ---------------- finalize + head ----------------
__global__ void finalize_z(const float* __restrict__ pool1, const float* __restrict__ pool2,
                           const float* __restrict__ cnt, const float* __restrict__ gb,
                           float* __restrict__ z)
{
    int i = blockIdx.x * blockDim.x + threadIdx.x;
    if (i >= GG * 256) return;
    int g = i >> 8, j = i & 255;
    float c = fmaxf(cnt[g], 1.f);
    float v;
    if (j < 128) v = pool1[g * 128 + j] / c;
    else v = pool2[g * 128 + (j - 128)] / c + gb[j - 128];
    z[i] = v;
}

__global__ __launch_bounds__(128) void head_kernel(
    const float* __restrict__ z,
    const float* __restrict__ w1, const float* __restrict__ b1,
    const float* __restrict__ w2, const float* __restrict__ b2,
    float* __restrict__ out)
{
    __shared__ float zs[256];
    __shared__ float hid[128];
    int g = blockIdx.x;
    int tid = threadIdx.x;
    zs[tid] = z[g * 256 + tid];
    zs[tid + 128] = z[g * 256 + 128 + tid];
    __syncthreads();
    float acc = b1[tid];
#pragma unroll 8
    for (int k = 0; k < 256; k++) acc += zs[k] * w1[k * 128 + tid];
    hid[tid] = fmaxf(acc, 0.f);
    __syncthreads();
    if (tid < 2) {
        float s = b2[tid];
        for (int k = 0; k < 128; k++) s += hid[k] * w2[k * 2 + tid];
        out[g * 2 + tid] = s;
    }
}

// ---------------- launch ----------------
static inline int cdiv(long long a, long long b) { return (int)((a + b - 1) / b); }

extern "C" void kernel_launch(void* const* d_in, const int* in_sizes, int n_in,
                              void* d_out, int out_size)
{
    const float* x     = (const float*)d_in[0];
    const int*   ei    = (const int*)  d_in[1];
    const float* ea    = (const float*)d_in[2];
    const int*   batch = (const int*)  d_in[3];
    const float* dwin  = (const float*)d_in[4];
    const float* dbin  = (const float*)d_in[5];
    const float* dwout = (const float*)d_in[6];
    const float* dbout = (const float*)d_in[7];
    const float* gwl   = (const float*)d_in[8];
    const float* gwr   = (const float*)d_in[9];
    const float* gwe   = (const float*)d_in[10];
    const float* gatt  = (const float*)d_in[11];
    const float* gb    = (const float*)d_in[12];
    const float* w1    = (const float*)d_in[13];
    const float* b1    = (const float*)d_in[14];
    const float* w2    = (const float*)d_in[15];
    const float* b2    = (const float*)d_in[16];

    const int nN = in_sizes[0] / 128;
    const int nE = in_sizes[1] / 2;
    const int* src = ei;
    const int* dst = ei + nE;

    void *pxh, *pAh, *pGl, *pGr, *pB, *pI, *pO, *pdi, *pdo, *prI, *prO, *pcI, *pcO,
         *ppI, *ppO, *pid, *pis, *psn, *pci, *pea, *pdn, *pco, *pc, *pp1, *pp2, *pz;
    cudaGetSymbolAddress(&pxh, g_xh);
    cudaGetSymbolAddress(&pAh, g_bufAh);
    cudaGetSymbolAddress(&pGl, g_glh);
    cudaGetSymbolAddress(&pGr, g_grh);
    cudaGetSymbolAddress(&pB, g_bufB);
    cudaGetSymbolAddress(&pI, g_aggI);
    cudaGetSymbolAddress(&pO, g_aggO);
    cudaGetSymbolAddress(&pdi, g_degi);
    cudaGetSymbolAddress(&pdo, g_dego);
    cudaGetSymbolAddress(&prI, g_rowI);
    cudaGetSymbolAddress(&prO, g_rowO);
    cudaGetSymbolAddress(&pcI, g_curI);
    cudaGetSymbolAddress(&pcO, g_curO);
    cudaGetSymbolAddress(&ppI, g_partI);
    cudaGetSymbolAddress(&ppO, g_partO);
    cudaGetSymbolAddress(&pid, g_dinvd);
    cudaGetSymbolAddress(&pis, g_dinvs);
    cudaGetSymbolAddress(&psn, g_snode);
    cudaGetSymbolAddress(&pci, g_coefI);
    cudaGetSymbolAddress(&pea, g_eaI);
    cudaGetSymbolAddress(&pdn, g_dnode);
    cudaGetSymbolAddress(&pco, g_coefO);
    cudaGetSymbolAddress(&pc, g_cnt);
    cudaGetSymbolAddress(&pp1, g_pool1);
    cudaGetSymbolAddress(&pp2, g_pool2);
    cudaGetSymbolAddress(&pz, g_z);

    __half* xh    = (__half*)pxh;
    __half* bufAh = (__half*)pAh;
    __half* glh   = (__half*)pGl;
    __half* grh   = (__half*)pGr;
    float* bufB  = (float*)pB;
    float* aggI  = (float*)pI;
    float* aggO  = (float*)pO;
    int*   degi  = (int*)pdi;
    int*   dego  = (int*)pdo;
    int*   rowI  = (int*)prI;
    int*   rowO  = (int*)prO;
    int*   curI  = (int*)pcI;
    int*   curO  = (int*)pcO;
    int*   partI = (int*)ppI;
    int*   partO = (int*)ppO;
    float* dinvd = (float*)pid;
    float* dinvs = (float*)pis;
    int*   snode = (int*)psn;
    float* coefI = (float*)pci;
    float* eaI   = (float*)pea;
    int*   dnode = (int*)pdn;
    float* coefO = (float*)pco;
    float* cnt   = (float*)pc;
    float* pool1 = (float*)pp1;
    float* pool2 = (float*)pp2;
    float* z     = (float*)pz;

    cudaFuncSetAttribute(gemm_dual, cudaFuncAttributeMaxDynamicSharedMemorySize, DUAL_SMEM);

    const int T = 256;
    const int nb = cdiv(nN, SCAN_BLK);
    const int gatherBlocks = cdiv((long long)nN * 32, T);

    // 1-3: setup
    zero_misc<<<cdiv(nN, T), T>>>(degi, dego, cnt, pool1, pool2, nN);
    deg_kernel<<<cdiv(nE, T), T>>>(src, dst, degi, dego, nE);
    dinv_kernel<<<cdiv(nN, T), T>>>(degi, dego, dinvd, dinvs, batch, cnt, nN);

    // 4: dual GAT transform (profiled by ncu), fp16 outputs
    gemm_dual<<<cdiv(nN, 128), T, DUAL_SMEM>>>(x, gwl, gwr, glh, grh, nN);

    // 5: x -> fp16
    cvt_x<<<cdiv((long long)nN * 64, T), T>>>((const float2*)x, (__half2*)xh,
                                              (long long)nN * 64);

    // 6-9: CSR build
    scanA<<<dim3(nb, 2), SCAN_BLK>>>(degi, dego, rowI, rowO, partI, partO, nN);
    scanB<<<2, 128>>>(partI, partO, nb);
    scanC<<<dim3(nb, 2), SCAN_BLK>>>(rowI, rowO, partI, partO, curI, curO, nN);
    build_perm<<<cdiv(nE, T), T>>>(src, dst, ea, dinvd, dinvs, curI, curO,
                                   snode, coefI, eaI, dnode, coefO, nE);

    // 10-12: DirGNN layer 0 (fp16 gathers -> fp32 agg -> GEMM -> fp16 bufA)
    gcn_gather<<<gatherBlocks, T>>>((const uint2*)xh, rowI, degi, snode, coefI, dinvd,
                                    (float4*)aggI, nN);
    gcn_gather<<<gatherBlocks, T>>>((const uint2*)xh, rowO, dego, dnode, coefO, dinvs,
                                    (float4*)aggO, nN);
    gemm_pair<true><<<cdiv(nN, 128), T>>>(aggO, dwout, dbout,
                                          aggI, dwin, dbin, bufAh, nN);

    // 13-15: DirGNN layer 1 -> fp32 bufB
    gcn_gather<<<gatherBlocks, T>>>((const uint2*)bufAh, rowI, degi, snode, coefI, dinvd,
                                    (float4*)aggI, nN);
    gcn_gather<<<gatherBlocks, T>>>((const uint2*)bufAh, rowO, dego, dnode, coefO, dinvs,
                                    (float4*)aggO, nN);
    gemm_pair<false><<<cdiv(nN, 128), T>>>(aggO, dwout + 128 * 128, dbout + 128,
                                           aggI, dwin + 128 * 128, dbin + 128, bufB, nN);

    // 16: fused GATv2 (fp16 gl/gr) -> out2 rows into aggI (free after L1 GEMM)
    gat_fused<<<gatherBlocks, T>>>((const uint2*)glh, (const uint2*)grh,
                                   rowI, degi, snode, eaI, gwe, gatt,
                                   (float4*)aggI, nN);

    // 17: mean pool sums
    pool_kernel<<<gatherBlocks, T>>>((const float4*)bufB, (const float4*)aggI,
                                     batch, pool1, pool2, nN);

    // 18-19: finalize + head
    finalize_z<<<cdiv(GG * 256, T), T>>>(pool1, pool2, cnt, gb, z);
    head_kernel<<<GG, 128>>>(z, w1, b1, w2, b2, (float*)d_out);
}